// round 1
// baseline (speedup 1.0000x reference)
#include <cuda_runtime.h>
#include <math.h>

#define NBLK 1184   // 148 SMs * 8 blocks
#define NTHR 256

__device__ float g_partial[NBLK];

// error_factor(t) * (o-t)^2   (0.5 and 1/N folded into the final kernel)
__device__ __forceinline__ float ef_term(float o, float t) {
    const float A         = 0.06444291424643259f;
    const float LOC       = -1.1328205299926424e-27f;
    const float INV_SCALE = (float)(1.0 / 1.5376362609160314);
    const float LOG_SCALE = 0.430438704527378f;           // ln(1.5376362609160314)
    const float INV_FX    = (float)(1.0 / 1.0500746950269468e+24);
    const float C         = (float)(1.0 / 107.2185);      // 1/(Y_MAX - Y_MIN)
    const float BETA      = 5.0f;
    const float LGAMMA_A  = 2.70804429f;                  // lnGamma(A)

    float x      = (t - LOC) * INV_SCALE;                 // > 0 even at t == 0
    float logpdf = (A - 1.0f) * __logf(x) - x - LGAMMA_A - LOG_SCALE;
    float pdf    = __expf(logpdf);
    float ef     = (BETA - C) * (1.0f - pdf * INV_FX) + C;
    float d      = o - t;
    return d * d * ef;
}

__global__ void __launch_bounds__(NTHR)
wes_reduce1(const float* __restrict__ outp, const float* __restrict__ targ,
            int n4, int n) {
    const float4* __restrict__ o4 = (const float4*)outp;
    const float4* __restrict__ t4 = (const float4*)targ;

    float acc = 0.0f;
    const int stride = gridDim.x * blockDim.x;
    int gtid = blockIdx.x * blockDim.x + threadIdx.x;

    for (int i = gtid; i < n4; i += stride) {
        float4 ov = o4[i];
        float4 tv = t4[i];
        acc += ef_term(ov.x, tv.x);
        acc += ef_term(ov.y, tv.y);
        acc += ef_term(ov.z, tv.z);
        acc += ef_term(ov.w, tv.w);
    }
    // scalar tail (n % 4 != 0 safety; no-op for this problem)
    for (int i = n4 * 4 + gtid; i < n; i += stride)
        acc += ef_term(outp[i], targ[i]);

    // warp reduce
    #pragma unroll
    for (int off = 16; off > 0; off >>= 1)
        acc += __shfl_down_sync(0xffffffffu, acc, off);

    __shared__ float smem[NTHR / 32];
    if ((threadIdx.x & 31) == 0) smem[threadIdx.x >> 5] = acc;
    __syncthreads();

    if (threadIdx.x < 32) {
        float v = (threadIdx.x < NTHR / 32) ? smem[threadIdx.x] : 0.0f;
        #pragma unroll
        for (int off = 16; off > 0; off >>= 1)
            v += __shfl_down_sync(0xffffffffu, v, off);
        if (threadIdx.x == 0) g_partial[blockIdx.x] = v;
    }
}

__global__ void __launch_bounds__(NTHR)
wes_reduce2(float* __restrict__ out, int n) {
    double acc = 0.0;
    for (int i = threadIdx.x; i < NBLK; i += blockDim.x)
        acc += (double)g_partial[i];

    #pragma unroll
    for (int off = 16; off > 0; off >>= 1)
        acc += __shfl_down_sync(0xffffffffu, acc, off);

    __shared__ double smem[NTHR / 32];
    if ((threadIdx.x & 31) == 0) smem[threadIdx.x >> 5] = acc;
    __syncthreads();

    if (threadIdx.x == 0) {
        double s = 0.0;
        #pragma unroll
        for (int w = 0; w < NTHR / 32; w++) s += smem[w];
        out[0] = (float)(s * 0.5 / (double)n);
    }
}

extern "C" void kernel_launch(void* const* d_in, const int* in_sizes, int n_in,
                              void* d_out, int out_size) {
    const float* outp = (const float*)d_in[0];  // "output" (normal)
    const float* targ = (const float*)d_in[1];  // "target" (uniform [0,1))
    int n  = in_sizes[0];
    int n4 = n >> 2;

    wes_reduce1<<<NBLK, NTHR>>>(outp, targ, n4, n);
    wes_reduce2<<<1, NTHR>>>((float*)d_out, n);
}

// round 2
// speedup vs baseline: 1.0291x; 1.0291x over previous
#include <cuda_runtime.h>
#include <math.h>

#define NBLK 1184   // 148 SMs * 8 blocks
#define NTHR 256

__device__ float        g_partial[NBLK];
__device__ unsigned int g_count;   // zero-initialized; self-resets via atomicInc wraparound

// Full error-factor path (only for t < ~1e-9, where pdf/FX_MAX matters in fp32)
__device__ __noinline__ float ef_rare(float t) {
    const float A         = 0.06444291424643259f;
    const float LOC       = -1.1328205299926424e-27f;
    const float INV_SCALE = (float)(1.0 / 1.5376362609160314);
    const float LOG_SCALE = 0.430438704527378f;           // ln(scale)
    const float INV_FX    = (float)(1.0 / 1.0500746950269468e+24);
    const float C         = (float)(1.0 / 107.2185);
    const float BETA      = 5.0f;
    const float LGAMMA_A  = 2.70804429f;                  // lnGamma(A)

    float x      = (t - LOC) * INV_SCALE;                 // > 0 even at t == 0
    float logpdf = (A - 1.0f) * __logf(x) - x - LGAMMA_A - LOG_SCALE;
    float pdf    = __expf(logpdf);
    return (BETA - C) * (1.0f - pdf * INV_FX) + C;
}

__device__ __forceinline__ float term(float o, float t) {
    const float BETA = 5.0f;
    float d  = o - t;
    float d2 = d * d;
    // For all t >= ~1.3e-19, (1 - pdf/FX_MAX) rounds to 1.0 in fp32 -> ef == BETA exactly.
    if (__builtin_expect(t < 1e-9f, 0))
        return d2 * ef_rare(t);
    return d2 * BETA;
}

__global__ void __launch_bounds__(NTHR)
wes_fused(const float* __restrict__ outp, const float* __restrict__ targ,
          int n4, int n, float* __restrict__ result) {
    const float4* __restrict__ o4 = (const float4*)outp;
    const float4* __restrict__ t4 = (const float4*)targ;

    float acc = 0.0f;
    const int stride = gridDim.x * blockDim.x;
    int gtid = blockIdx.x * blockDim.x + threadIdx.x;

    for (int i = gtid; i < n4; i += stride) {
        float4 ov = __ldcs(&o4[i]);
        float4 tv = __ldcs(&t4[i]);
        acc += term(ov.x, tv.x);
        acc += term(ov.y, tv.y);
        acc += term(ov.z, tv.z);
        acc += term(ov.w, tv.w);
    }
    for (int i = n4 * 4 + gtid; i < n; i += stride)      // tail safety (no-op here)
        acc += term(outp[i], targ[i]);

    // intra-block reduction
    #pragma unroll
    for (int off = 16; off > 0; off >>= 1)
        acc += __shfl_down_sync(0xffffffffu, acc, off);

    __shared__ float smem[NTHR / 32];
    if ((threadIdx.x & 31) == 0) smem[threadIdx.x >> 5] = acc;
    __syncthreads();

    __shared__ bool is_last;
    if (threadIdx.x == 0) {
        float v = 0.0f;
        #pragma unroll
        for (int w = 0; w < NTHR / 32; w++) v += smem[w];
        g_partial[blockIdx.x] = v;
        __threadfence();
        // counts 1..NBLK-1 then wraps to 0 on the NBLK-th increment -> self-resetting
        unsigned old = atomicInc(&g_count, NBLK - 1);
        is_last = (old == NBLK - 1);
    }
    __syncthreads();

    if (is_last) {
        double dacc = 0.0;
        for (int i = threadIdx.x; i < NBLK; i += NTHR)
            dacc += (double)g_partial[i];
        #pragma unroll
        for (int off = 16; off > 0; off >>= 1)
            dacc += __shfl_down_sync(0xffffffffu, dacc, off);

        __shared__ double dmem[NTHR / 32];
        if ((threadIdx.x & 31) == 0) dmem[threadIdx.x >> 5] = dacc;
        __syncthreads();
        if (threadIdx.x == 0) {
            double s = 0.0;
            #pragma unroll
            for (int w = 0; w < NTHR / 32; w++) s += dmem[w];
            result[0] = (float)(s * 0.5 / (double)n);
        }
    }
}

extern "C" void kernel_launch(void* const* d_in, const int* in_sizes, int n_in,
                              void* d_out, int out_size) {
    const float* outp = (const float*)d_in[0];
    const float* targ = (const float*)d_in[1];
    int n  = in_sizes[0];
    int n4 = n >> 2;

    wes_fused<<<NBLK, NTHR>>>(outp, targ, n4, n, (float*)d_out);
}